// round 9
// baseline (speedup 1.0000x reference)
#include <cuda_runtime.h>
#include <cuda_bf16.h>
#include <cstdint>
#include <math.h>

typedef __nv_bfloat16 bf16;
#define B_ 4
#define NG 1024
#define NC 1024
#define NQ 256
#define NF 512
#define NH 8
#define HD 64

// ---------------- helpers ----------------
__device__ __forceinline__ uint32_t smem_u32(const void* p) {
    uint32_t a; asm("{ .reg .u64 t; cvta.to.shared.u64 t, %1; cvt.u32.u64 %0, t; }" : "=r"(a) : "l"(p));
    return a;
}
#define SW128(x) ((x) ^ (((x) >> 3) & 0x70))
__device__ __forceinline__ void ldsm4(uint32_t& r0, uint32_t& r1, uint32_t& r2, uint32_t& r3, uint32_t a) {
    asm volatile("ldmatrix.sync.aligned.m8n8.x4.shared.b16 {%0,%1,%2,%3}, [%4];"
                 : "=r"(r0), "=r"(r1), "=r"(r2), "=r"(r3) : "r"(a));
}
__device__ __forceinline__ void mma_bf16(float* c, const uint32_t* a, const uint32_t* b) {
    asm volatile("mma.sync.aligned.m16n8k16.row.col.f32.bf16.bf16.f32 "
                 "{%0,%1,%2,%3}, {%4,%5,%6,%7}, {%8,%9}, {%0,%1,%2,%3};"
                 : "+f"(c[0]), "+f"(c[1]), "+f"(c[2]), "+f"(c[3])
                 : "r"(a[0]), "r"(a[1]), "r"(a[2]), "r"(a[3]), "r"(b[0]), "r"(b[1]));
}
#define CP16(d, s) asm volatile("cp.async.cg.shared.global [%0], [%1], 16;" :: "r"(d), "l"(s))
#define CPC() asm volatile("cp.async.commit_group;" ::: "memory")
template<int N> __device__ __forceinline__ void cpwait() {
    asm volatile("cp.async.wait_group %0;" :: "n"(N) : "memory");
}
__device__ __forceinline__ uint32_t pack2(bf16 a, bf16 b) {
    return (uint32_t)__bfloat16_as_ushort(a) | ((uint32_t)__bfloat16_as_ushort(b) << 16);
}

// ---------------- device scratch ----------------
__device__ bf16 g_fWh[8u*1024*1024], g_fWl[8u*1024*1024];   // interleaved fusion weights
__device__ bf16 g_aWh[6u*512*512],  g_aWl[6u*512*512];
__device__ bf16 g_adjTb[4u*1024*1024];
__device__ unsigned char g_cg[4u*1024*1024], g_gc[4u*1024*1024];
__device__ unsigned char g_gq[4u*1024*256],  g_qg[4u*256*1024];
__device__ bf16 g_Gth[4u*512*1024], g_Gtl[4u*512*1024];
__device__ bf16 g_catC_h[4194304], g_catC_l[4194304];
__device__ bf16 g_catG1_h[4194304], g_catG1_l[4194304];
__device__ bf16 g_catQ_h[1048576], g_catQ_l[1048576];
__device__ bf16 g_catG2_h[4194304], g_catG2_l[4194304];
__device__ bf16 g_Vth[6291456], g_Vtl[6291456];
__device__ float g_PG[4096u*1536], g_PC[4096u*512], g_PQ[1024u*1024];
__device__ float g_G1[4096u*512];
__device__ float g_Ga[4096u*512], g_Ca[4096u*512], g_Qa[1024u*512];
__device__ float g_s1[98304], g_Ep1[98304], g_En1[98304];
__device__ float g_s2[98304], g_Ep2[98304], g_En2[98304];
__device__ float g_icS[98304];

// ---------------- pipelined mma.sync GEMM (R6, verbatim) ----------------
template<int NPASS, int TN>
__device__ __forceinline__ void stage_chunk(uint32_t sdst, const char* smbase,
    const bf16* Ah, const bf16* Al, const bf16* Bh, const bf16* Bl,
    int lda, int ldb, int m0, int n0, int k0, int tid)
{
    constexpr int ASZ = 16384;
    constexpr int ABY = (NPASS == 3) ? 32768 : 16384;
    constexpr int BSZ = TN * 128;
    (void)smbase;
#pragma unroll 2
    for (int i = tid; i < 128 * 8; i += 256) {
        int r = i >> 3, c = i & 7;
        uint32_t off = SW128((r << 7) + (c << 4));
        size_t go = (size_t)(m0 + r) * lda + k0 + (c << 3);
        CP16(sdst + off, Ah + go);
        if (NPASS == 3) CP16(sdst + ASZ + off, Al + go);
    }
#pragma unroll 2
    for (int i = tid; i < TN * 8; i += 256) {
        int r = i >> 3, c = i & 7;
        uint32_t off = SW128((r << 7) + (c << 4));
        size_t go = (size_t)(n0 + r) * ldb + k0 + (c << 3);
        CP16(sdst + ABY + off, Bh + go);
        CP16(sdst + ABY + BSZ + off, Bl + go);
    }
    CPC();
}

template<int NPASS, int TN, int EPI>
__global__ void __launch_bounds__(256) gemm_mm(
    const bf16* __restrict__ Ah, const bf16* __restrict__ Al,
    const bf16* __restrict__ Bh, const bf16* __restrict__ Bl,
    float* __restrict__ C, bf16* __restrict__ Dh, bf16* __restrict__ Dl,
    int K, int lda, int ldb, int ldc, long sA, long sB, long sC)
{
    constexpr int WN = 4;
    constexpr int TMW = 64;
    constexpr int MT = 4;
    constexpr int NT = (TN / WN) / 8;
    constexpr int ASZ = 16384;
    constexpr int ABY = (NPASS == 3) ? 32768 : 16384;
    constexpr int BSZ = TN * 128;
    constexpr int STG = ABY + 2 * BSZ;
    extern __shared__ char sm[];
    const uint32_t sbase = smem_u32(sm);
    const int tid = threadIdx.x, lane = tid & 31;
    const int wid = tid >> 5;
    const int wm = wid / WN, wn = wid % WN;
    const int z = blockIdx.z;
    const int m0 = blockIdx.y * 128, n0 = blockIdx.x * TN;
    const bf16* Azh = Ah + (size_t)z * sA;
    const bf16* Azl = Al + (size_t)z * sA;
    const bf16* Bzh = Bh + (size_t)z * sB;
    const bf16* Bzl = Bl + (size_t)z * sB;

    float acc[MT][NT][4];
#pragma unroll
    for (int i = 0; i < MT; i++)
#pragma unroll
        for (int j = 0; j < NT; j++)
#pragma unroll
            for (int v = 0; v < 4; v++) acc[i][j][v] = 0.f;

    const int rsel = lane & 15, csel = lane >> 4;
    const int nch = K >> 6;
    stage_chunk<NPASS, TN>(sbase, sm, Azh, Azl, Bzh, Bzl, lda, ldb, m0, n0, 0, tid);
    for (int kc = 0; kc < nch; kc++) {
        if (kc + 1 < nch) {
            stage_chunk<NPASS, TN>(sbase + ((kc + 1) & 1) * STG, sm, Azh, Azl, Bzh, Bzl,
                                   lda, ldb, m0, n0, (kc + 1) << 6, tid);
            cpwait<1>();
        } else {
            cpwait<0>();
        }
        __syncthreads();
        const uint32_t aH = sbase + (kc & 1) * STG;
        const uint32_t aL = aH + ASZ;
        const uint32_t bH = aH + ABY;
        const uint32_t bL = bH + BSZ;
#pragma unroll
        for (int ks = 0; ks < 4; ks++) {
            uint32_t ah[MT][4], al[MT][4], bh[NT][2], bl[NT][2];
#pragma unroll
            for (int mt = 0; mt < MT; mt++) {
                int row = wm * TMW + mt * 16 + rsel;
                uint32_t off = SW128((row << 7) + ((ks * 2 + csel) << 4));
                ldsm4(ah[mt][0], ah[mt][1], ah[mt][2], ah[mt][3], aH + off);
                if (NPASS == 3)
                    ldsm4(al[mt][0], al[mt][1], al[mt][2], al[mt][3], aL + off);
            }
#pragma unroll
            for (int np = 0; np < NT / 2; np++) {
                int nr = wn * (TN / WN) + np * 16 + rsel;
                uint32_t off = SW128((nr << 7) + ((ks * 2 + csel) << 4));
                uint32_t r0, r1, r2, r3;
                ldsm4(r0, r1, r2, r3, bH + off);
                bh[2*np][0] = r0; bh[2*np+1][0] = r1; bh[2*np][1] = r2; bh[2*np+1][1] = r3;
                ldsm4(r0, r1, r2, r3, bL + off);
                bl[2*np][0] = r0; bl[2*np+1][0] = r1; bl[2*np][1] = r2; bl[2*np+1][1] = r3;
            }
#pragma unroll
            for (int mt = 0; mt < MT; mt++)
#pragma unroll
                for (int nt = 0; nt < NT; nt++) {
                    mma_bf16(acc[mt][nt], ah[mt], bh[nt]);
                    mma_bf16(acc[mt][nt], ah[mt], bl[nt]);
                    if (NPASS == 3) mma_bf16(acc[mt][nt], al[mt], bh[nt]);
                }
        }
        __syncthreads();
    }
    if (EPI == 0) {
        float* Cz = C + (size_t)z * sC;
#pragma unroll
        for (int mt = 0; mt < MT; mt++) {
            int row = m0 + wm * TMW + mt * 16 + (lane >> 2);
#pragma unroll
            for (int nt = 0; nt < NT; nt++) {
                int col = n0 + wn * (TN / WN) + nt * 8 + ((lane & 3) << 1);
                float2 p0 = {acc[mt][nt][0], acc[mt][nt][1]};
                float2 p1 = {acc[mt][nt][2], acc[mt][nt][3]};
                *(float2*)&Cz[(size_t)row * ldc + col] = p0;
                *(float2*)&Cz[(size_t)(row + 8) * ldc + col] = p1;
            }
        }
    } else {
        bf16* Dzh = Dh + (size_t)z * sC;
        bf16* Dzl = Dl + (size_t)z * sC;
#pragma unroll
        for (int mt = 0; mt < MT; mt++) {
            int row = m0 + wm * TMW + mt * 16 + (lane >> 2);
#pragma unroll
            for (int nt = 0; nt < NT; nt++) {
                int col = n0 + wn * (TN / WN) + nt * 8 + ((lane & 3) << 1);
                float v0 = acc[mt][nt][0], v1 = acc[mt][nt][1];
                float v2 = acc[mt][nt][2], v3 = acc[mt][nt][3];
                bf16 h0 = __float2bfloat16(v0), h1 = __float2bfloat16(v1);
                bf16 h2 = __float2bfloat16(v2), h3 = __float2bfloat16(v3);
                *(uint32_t*)&Dzh[(size_t)row * ldc + col] = pack2(h0, h1);
                *(uint32_t*)&Dzh[(size_t)(row + 8) * ldc + col] = pack2(h2, h3);
                *(uint32_t*)&Dzl[(size_t)row * ldc + col] =
                    pack2(__float2bfloat16(v0 - __bfloat162float(h0)),
                          __float2bfloat16(v1 - __bfloat162float(h1)));
                *(uint32_t*)&Dzl[(size_t)(row + 8) * ldc + col] =
                    pack2(__float2bfloat16(v2 - __bfloat162float(h2)),
                          __float2bfloat16(v3 - __bfloat162float(h3)));
            }
        }
    }
}

// ---------------- fusion GEMM with gated epilogue (plain args) ----------------
__global__ void __launch_bounds__(256) gemm_fus(
    const bf16* __restrict__ Ah, const bf16* __restrict__ Al,
    const bf16* __restrict__ Bh, const bf16* __restrict__ Bl,
    const float* __restrict__ a, float* __restrict__ out,
    bf16* __restrict__ Dh, bf16* __restrict__ Dl, int wsplit)
{
    constexpr int ASZ = 16384, ABY = 32768, BSZ = 16384, STG = 65536;
    extern __shared__ char sm[];
    const uint32_t sbase = smem_u32(sm);
    const int tid = threadIdx.x, lane = tid & 31, wid = tid >> 5;
    const int wm = wid >> 2, wn = wid & 3;
    const int m0 = blockIdx.y * 128, n0 = blockIdx.x * 128;

    float acc[4][4][4];
#pragma unroll
    for (int i = 0; i < 4; i++)
#pragma unroll
        for (int j = 0; j < 4; j++)
#pragma unroll
            for (int v = 0; v < 4; v++) acc[i][j][v] = 0.f;

#define FSTAGE(kc, st) do { \
    const int k0_ = (kc) << 6; \
    const uint32_t sd_ = sbase + (st) * STG; \
    for (int i = tid; i < 128 * 8; i += 256) { \
        int r_ = i >> 3, c_ = i & 7; \
        uint32_t off_ = SW128((r_ << 7) + (c_ << 4)); \
        size_t go_ = (size_t)(m0 + r_) * 1024 + k0_ + (c_ << 3); \
        CP16(sd_ + off_, Ah + go_); \
        CP16(sd_ + ASZ + off_, Al + go_); \
        size_t gb_ = (size_t)(n0 + r_) * 1024 + k0_ + (c_ << 3); \
        CP16(sd_ + ABY + off_, Bh + gb_); \
        CP16(sd_ + ABY + BSZ + off_, Bl + gb_); \
    } \
    CPC(); } while (0)

    const int rsel = lane & 15, csel = lane >> 4;
    FSTAGE(0, 0);
    for (int kc = 0; kc < 16; kc++) {
        if (kc + 1 < 16) { FSTAGE(kc + 1, (kc + 1) & 1); cpwait<1>(); }
        else cpwait<0>();
        __syncthreads();
        const uint32_t aH = sbase + (kc & 1) * STG;
        const uint32_t aL = aH + ASZ, bH = aH + ABY, bL = bH + BSZ;
#pragma unroll
        for (int ks = 0; ks < 4; ks++) {
            uint32_t ah[4][4], al[4][4], bh[4][2], bl[4][2];
#pragma unroll
            for (int mt = 0; mt < 4; mt++) {
                int row = wm * 64 + mt * 16 + rsel;
                uint32_t off = SW128((row << 7) + ((ks * 2 + csel) << 4));
                ldsm4(ah[mt][0], ah[mt][1], ah[mt][2], ah[mt][3], aH + off);
                ldsm4(al[mt][0], al[mt][1], al[mt][2], al[mt][3], aL + off);
            }
#pragma unroll
            for (int np = 0; np < 2; np++) {
                int nr = wn * 32 + np * 16 + rsel;
                uint32_t off = SW128((nr << 7) + ((ks * 2 + csel) << 4));
                uint32_t r0, r1, r2, r3;
                ldsm4(r0, r1, r2, r3, bH + off);
                bh[2*np][0] = r0; bh[2*np+1][0] = r1; bh[2*np][1] = r2; bh[2*np+1][1] = r3;
                ldsm4(r0, r1, r2, r3, bL + off);
                bl[2*np][0] = r0; bl[2*np+1][0] = r1; bl[2*np][1] = r2; bl[2*np+1][1] = r3;
            }
#pragma unroll
            for (int mt = 0; mt < 4; mt++)
#pragma unroll
                for (int nt = 0; nt < 4; nt++) {
                    mma_bf16(acc[mt][nt], ah[mt], bh[nt]);
                    mma_bf16(acc[mt][nt], ah[mt], bl[nt]);
                    mma_bf16(acc[mt][nt], al[mt], bh[nt]);
                }
        }
        __syncthreads();
    }
#undef FSTAGE
    // gated epilogue: even col = new_a, odd col = gate pre-sigmoid
#pragma unroll
    for (int mt = 0; mt < 4; mt++) {
        int row = m0 + wm * 64 + mt * 16 + (lane >> 2);
#pragma unroll
        for (int nt = 0; nt < 4; nt++) {
            int f0 = (n0 >> 1) + wn * 16 + nt * 4 + (lane & 3);
            float t1a = acc[mt][nt][0], t2a = acc[mt][nt][1];
            float t1b = acc[mt][nt][2], t2b = acc[mt][nt][3];
            float ga = 1.f / (1.f + expf(-t2a));
            float gb = 1.f / (1.f + expf(-t2b));
            float aa = a[(size_t)row * 512 + f0];
            float ab = a[(size_t)(row + 8) * 512 + f0];
            float o0 = ga * t1a + (1.f - ga) * aa;
            float o1 = gb * t1b + (1.f - gb) * ab;
            out[(size_t)row * 512 + f0] = o0;
            out[(size_t)(row + 8) * 512 + f0] = o1;
            if (wsplit) {
                bf16 h0 = __float2bfloat16(o0), h1 = __float2bfloat16(o1);
                Dh[(size_t)row * 1024 + f0] = h0;
                Dh[(size_t)(row + 8) * 1024 + f0] = h1;
                Dl[(size_t)row * 1024 + f0] = __float2bfloat16(o0 - __bfloat162float(h0));
                Dl[(size_t)(row + 8) * 1024 + f0] = __float2bfloat16(o1 - __bfloat162float(h1));
            }
        }
    }
}

// ---------------- fused attention AV (R6, verbatim) ----------------
__global__ void __launch_bounds__(256) attn_av2(
    const unsigned char* __restrict__ adjnm,
    const float* __restrict__ s1, const float* __restrict__ Ep1, const float* __restrict__ En1,
    const float* __restrict__ s2, const float* __restrict__ Ep2, const float* __restrict__ En2,
    const bf16* __restrict__ Vth, const bf16* __restrict__ Vtl,
    bf16* __restrict__ Dh, bf16* __restrict__ Dl, int N, int M)
{
    constexpr int ASZ = 16384;
    constexpr int ABY = 32768;
    constexpr int BSZ = 8192;
    constexpr int STG = 49152;
    constexpr int TN = 64, WN = 2, TMW = 32, MT = 2, NT = 4;
    extern __shared__ char sm[];
    const uint32_t sbase = smem_u32(sm);
    const int tid = threadIdx.x, lane = tid & 31;
    const int wid = tid >> 5;
    const int wm = wid >> 1, wn = wid & 1;
    const int z = blockIdx.z, b = z >> 3;
    const int n0 = blockIdx.y * 128;
    const bf16* Vzh = Vth + (size_t)z * 64 * M;
    const bf16* Vzl = Vtl + (size_t)z * 64 * M;
    const size_t zN = (size_t)z * N, zM = (size_t)z * M;
    const int nl = tid & 127, half = tid >> 7;
    const int ng = n0 + nl;
    const float s1v = s1[zN + ng], p1 = Ep1[zN + ng], n1v = En1[zN + ng];
    const unsigned char* arow = adjnm + ((size_t)b * N + ng) * M;
    const uint32_t rowoff = (nl << 7) + (half << 6);

#define VSTAGE(kc, st) do { \
    const int k0_ = (kc) << 6; \
    const uint32_t sd_ = sbase + (st) * STG + ABY; \
    for (int i = tid; i < 64 * 8; i += 256) { \
        int r_ = i >> 3, c_ = i & 7; \
        uint32_t off_ = SW128((r_ << 7) + (c_ << 4)); \
        size_t go_ = (size_t)r_ * M + k0_ + (c_ << 3); \
        CP16(sd_ + off_, Vzh + go_); \
        CP16(sd_ + BSZ + off_, Vzl + go_); \
    } \
    CPC(); } while (0)

#define PBUILD(kc, st) do { \
    const int mb_ = ((kc) << 6) + half * 32; \
    union { uint4 v; unsigned char c[16]; } a0_, a1_; \
    a0_.v = *(const uint4*)(arow + mb_); \
    a1_.v = *(const uint4*)(arow + mb_ + 16); \
    float wv_[32]; \
    _Pragma("unroll") \
    for (int j = 0; j < 32; j++) { \
        unsigned char aj = (j < 16) ? a0_.c[j] : a1_.c[j - 16]; \
        float w = 0.f; \
        if (aj) { \
            size_t o2 = zM + mb_ + j; \
            w = (s1v + s2[o2] > 0.f) ? p1 * Ep2[o2] : n1v * En2[o2]; \
        } \
        wv_[j] = w; \
    } \
    char* dst_ = sm + (st) * STG; \
    _Pragma("unroll") \
    for (int g = 0; g < 4; g++) { \
        uint32_t hp_[4], lp_[4]; \
        _Pragma("unroll") \
        for (int q = 0; q < 4; q++) { \
            float va = wv_[g * 8 + q * 2], vb = wv_[g * 8 + q * 2 + 1]; \
            bf16 ha = __float2bfloat16(va), hb = __float2bfloat16(vb); \
            hp_[q] = pack2(ha, hb); \
            lp_[q] = pack2(__float2bfloat16(va - __bfloat162float(ha)), \
                           __float2bfloat16(vb - __bfloat162float(hb))); \
        } \
        uint32_t off_ = SW128(rowoff + (g << 4)); \
        *(uint4*)(dst_ + off_) = make_uint4(hp_[0], hp_[1], hp_[2], hp_[3]); \
        *(uint4*)(dst_ + ASZ + off_) = make_uint4(lp_[0], lp_[1], lp_[2], lp_[3]); \
    } } while (0)

    float acc[MT][NT][4];
#pragma unroll
    for (int i = 0; i < MT; i++)
#pragma unroll
        for (int j = 0; j < NT; j++)
#pragma unroll
            for (int v = 0; v < 4; v++) acc[i][j][v] = 0.f;

    const int rsel = lane & 15, csel = lane >> 4;
    const int nch = M >> 6;
    VSTAGE(0, 0);
    PBUILD(0, 0);
    for (int kc = 0; kc < nch; kc++) {
        if (kc + 1 < nch) { VSTAGE(kc + 1, (kc + 1) & 1); cpwait<1>(); }
        else cpwait<0>();
        __syncthreads();
        const uint32_t aH = sbase + (kc & 1) * STG;
        const uint32_t aL = aH + ASZ, bH = aH + ABY, bL = bH + BSZ;
#pragma unroll
        for (int ks = 0; ks < 4; ks++) {
            uint32_t ah[MT][4], al[MT][4], bh[NT][2], bl[NT][2];
#pragma unroll
            for (int mt = 0; mt < MT; mt++) {
                int row = wm * 32 + mt * 16 + rsel;
                uint32_t off = SW128((row << 7) + ((ks * 2 + csel) << 4));
                ldsm4(ah[mt][0], ah[mt][1], ah[mt][2], ah[mt][3], aH + off);
                ldsm4(al[mt][0], al[mt][1], al[mt][2], al[mt][3], aL + off);
            }
#pragma unroll
            for (int np = 0; np < 2; np++) {
                int nr = wn * 32 + np * 16 + rsel;
                uint32_t off = SW128((nr << 7) + ((ks * 2 + csel) << 4));
                uint32_t r0, r1, r2, r3;
                ldsm4(r0, r1, r2, r3, bH + off);
                bh[2*np][0] = r0; bh[2*np+1][0] = r1; bh[2*np][1] = r2; bh[2*np+1][1] = r3;
                ldsm4(r0, r1, r2, r3, bL + off);
                bl[2*np][0] = r0; bl[2*np+1][0] = r1; bl[2*np][1] = r2; bl[2*np+1][1] = r3;
            }
#pragma unroll
            for (int mt = 0; mt < MT; mt++)
#pragma unroll
                for (int nt = 0; nt < NT; nt++) {
                    mma_bf16(acc[mt][nt], ah[mt], bh[nt]);
                    mma_bf16(acc[mt][nt], ah[mt], bl[nt]);
                    mma_bf16(acc[mt][nt], al[mt], bh[nt]);
                }
        }
        __syncthreads();
        if (kc + 1 < nch) PBUILD(kc + 1, (kc + 1) & 1);
    }
#undef VSTAGE
#undef PBUILD
    bf16* Dzh = Dh + (size_t)b * N * 1024 + (z & 7) * 64;
    bf16* Dzl = Dl + (size_t)b * N * 1024 + (z & 7) * 64;
#pragma unroll
    for (int mt = 0; mt < MT; mt++) {
        int row = n0 + wm * 32 + mt * 16 + (lane >> 2);
#pragma unroll
        for (int nt = 0; nt < NT; nt++) {
            int col = wn * 32 + nt * 8 + ((lane & 3) << 1);
            float v0 = acc[mt][nt][0], v1 = acc[mt][nt][1];
            float v2 = acc[mt][nt][2], v3 = acc[mt][nt][3];
            v0 = v0 > 0.f ? v0 : expm1f(v0);
            v1 = v1 > 0.f ? v1 : expm1f(v1);
            v2 = v2 > 0.f ? v2 : expm1f(v2);
            v3 = v3 > 0.f ? v3 : expm1f(v3);
            bf16 h0 = __float2bfloat16(v0), h1 = __float2bfloat16(v1);
            bf16 h2 = __float2bfloat16(v2), h3 = __float2bfloat16(v3);
            *(uint32_t*)&Dzh[(size_t)row * 1024 + col] = pack2(h0, h1);
            *(uint32_t*)&Dzh[(size_t)(row + 8) * 1024 + col] = pack2(h2, h3);
            *(uint32_t*)&Dzl[(size_t)row * 1024 + col] =
                pack2(__float2bfloat16(v0 - __bfloat162float(h0)),
                      __float2bfloat16(v1 - __bfloat162float(h1)));
            *(uint32_t*)&Dzl[(size_t)(row + 8) * 1024 + col] =
                pack2(__float2bfloat16(v2 - __bfloat162float(h2)),
                      __float2bfloat16(v3 - __bfloat162float(h3)));
        }
    }
}

// ---------------- prep / pointwise ----------------
__global__ void prep_fusW(const float* W, const float* U, const float* Wf, const float* Uf) {
    int i = blockIdx.x * 256 + threadIdx.x;
    int zi = blockIdx.y;
    if (i >= 1024 * 1024) return;
    int n = i >> 10, k = i & 1023;
    int f = n >> 1, gate = n & 1;
    size_t base = (size_t)zi * 512 * 512;
    float v;
    if (!gate) v = (k < 512) ? W[base + (size_t)k*512 + f] : U[base + (size_t)(k-512)*512 + f];
    else       v = (k < 512) ? Wf[base + (size_t)k*512 + f] : Uf[base + (size_t)(k-512)*512 + f];
    bf16 h = __float2bfloat16(v);
    g_fWh[(size_t)zi * 1048576 + i] = h;
    g_fWl[(size_t)zi * 1048576 + i] = __float2bfloat16(v - __bfloat162float(h));
}
struct WTab { const float* W[6]; };
__global__ void prep_attW6(WTab t) {
    int slot = blockIdx.y;
    int i = blockIdx.x * 256 + threadIdx.x;
    if (i >= 512 * 512) return;
    int n = i >> 9, k = i & 511;
    float v = t.W[slot][((size_t)((n >> 6) * 512 + k)) * 64 + (n & 63)];
    bf16 h = __float2bfloat16(v);
    g_aWh[(size_t)slot * 262144 + i] = h;
    g_aWl[(size_t)slot * 262144 + i] = __float2bfloat16(v - __bfloat162float(h));
}
__global__ void prep_adj_cg(const int* adj) {
    int i = blockIdx.x * 256 + threadIdx.x; int b = blockIdx.y;
    if (i >= NG * NC) return;
    int gi = i >> 10, c = i & 1023;
    int a = adj[(size_t)b * NG * NC + i];
    unsigned char u = (a > 0);
    g_gc[(size_t)b * NG * NC + i] = u;
    size_t t = (size_t)b * NG * NC + (size_t)c * NG + gi;
    g_cg[t] = u;
    g_adjTb[t] = __float2bfloat16((float)a);
}
__global__ void prep_adj_gq(const int* adj) {
    int i = blockIdx.x * 256 + threadIdx.x; int b = blockIdx.y;
    if (i >= NG * NQ) return;
    int gi = i >> 8, q = i & 255;
    unsigned char u = (adj[(size_t)b * NG * NQ + i] > 0);
    g_gq[(size_t)b * NG * NQ + i] = u;
    g_qg[(size_t)b * NQ * NG + (size_t)q * NG + gi] = u;
}
struct SCTab { const float* src[3]; bf16* dh[3]; bf16* dl[3]; int tot[3]; };
__global__ void split_cat3(SCTab t) {
    int seg = blockIdx.y;
    int i = blockIdx.x * 256 + threadIdx.x;
    if (i >= t.tot[seg]) return;
    int m = i >> 9, f = i & 511;
    float v = t.src[seg][i];
    bf16 h = __float2bfloat16(v);
    size_t o = (size_t)m * 1024 + f;
    t.dh[seg][o] = h;
    t.dl[seg][o] = __float2bfloat16(v - __bfloat162float(h));
}
__global__ void tsplit_k(const float* __restrict__ src) {
    int i = blockIdx.x * 256 + threadIdx.x; int b = blockIdx.y;
    if (i >= NF * NG) return;
    int f = i >> 10, gi = i & 1023;
    float v = src[((size_t)b * NG + gi) * NF + f];
    bf16 h = __float2bfloat16(v);
    size_t o = (size_t)b * NF * NG + i;
    g_Gth[o] = h; g_Gtl[o] = __float2bfloat16(v - __bfloat162float(h));
}
struct SE { const float* P; const float* av; float *s, *Ep, *En; int Nt, ldP, coff; };
struct SE6 { SE e[6]; };
__global__ void scores6(SE6 t) {
    SE e = t.e[blockIdx.y];
    int i = blockIdx.x * 256 + threadIdx.x;
    if (i >= 32 * e.Nt) return;
    int n = i % e.Nt, bh = i / e.Nt, h = bh & 7, b = bh >> 3;
    const float* row = e.P + ((size_t)b * e.Nt + n) * e.ldP + e.coff + h * 64;
    const float* av = e.av + h * 64;
    float acc = 0.f;
#pragma unroll
    for (int d = 0; d < 64; d++) acc += row[d] * av[d];
    e.s[i] = acc; e.Ep[i] = expf(acc); e.En[i] = expf(0.2f * acc);
}
struct CE { const unsigned char* adjmn; const float *s1, *Ep1, *En1, *s2, *Ep2, *En2;
            float* icS; int N, M; };
struct CE3 { CE e[3]; };
__global__ void colsum3(CE3 t) {
    CE e = t.e[blockIdx.z];
    int b = blockIdx.y;
    int w = threadIdx.x >> 5, lane = threadIdx.x & 31;
    int m = blockIdx.x * 8 + w;
    if (m >= e.M) return;
    const unsigned char* arow = e.adjmn + ((size_t)b * e.M + m) * e.N;
    float s2v[8], Sp[8] = {}, Sn[8] = {};
#pragma unroll
    for (int h = 0; h < 8; h++) s2v[h] = e.s2[((size_t)(b * 8 + h)) * e.M + m];
    for (int n = lane; n < e.N; n += 32) {
        if (!arow[n]) continue;
#pragma unroll
        for (int h = 0; h < 8; h++) {
            size_t o = ((size_t)(b * 8 + h)) * e.N + n;
            if (e.s1[o] + s2v[h] > 0.f) Sp[h] += e.Ep1[o]; else Sn[h] += e.En1[o];
        }
    }
#pragma unroll
    for (int h = 0; h < 8; h++) {
        float p = Sp[h], q = Sn[h];
        for (int d = 16; d; d >>= 1) { p += __shfl_xor_sync(~0u, p, d); q += __shfl_xor_sync(~0u, q, d); }
        if (lane == 0) {
            size_t o = ((size_t)(b * 8 + h)) * e.M + m;
            e.icS[o] = 1.f / (e.Ep2[o] * p + e.En2[o] * q);
        }
    }
}
struct VE { const float* Pk; const float* icS; bf16 *Vth, *Vtl; int M, ldP, coff; };
struct VE3 { VE e[3]; };
__global__ void vtprep3(VE3 t) {
    VE e = t.e[blockIdx.y];
    int z = blockIdx.z, b = z >> 3, h = z & 7;
    int i = blockIdx.x * 256 + threadIdx.x;
    if (i >= 64 * e.M) return;
    int d = i / e.M, m = i % e.M;
    float v = e.Pk[((size_t)b * e.M + m) * e.ldP + e.coff + h * 64 + d] * e.icS[(size_t)z * e.M + m];
    bf16 hh = __float2bfloat16(v);
    size_t o = (size_t)z * 64 * e.M + i;
    e.Vth[o] = hh; e.Vtl[o] = __float2bfloat16(v - __bfloat162float(hh));
}

// ---------------- host ----------------
template<typename T> static T* sa(const void* s) { void* p = nullptr; cudaGetSymbolAddress(&p, s); return (T*)p; }

extern "C" void kernel_launch(void* const* d_in, const int* in_sizes, int n_in,
                              void* d_out, int out_size) {
    (void)in_sizes; (void)n_in; (void)out_size;
    bf16 *fWh = sa<bf16>(g_fWh), *fWl = sa<bf16>(g_fWl);
    bf16 *aWh = sa<bf16>(g_aWh), *aWl = sa<bf16>(g_aWl);
    bf16 *adjTb = sa<bf16>(g_adjTb);
    bf16 *Gth = sa<bf16>(g_Gth), *Gtl = sa<bf16>(g_Gtl);
    bf16 *catCh = sa<bf16>(g_catC_h), *catCl = sa<bf16>(g_catC_l);
    bf16 *catG1h = sa<bf16>(g_catG1_h), *catG1l = sa<bf16>(g_catG1_l);
    bf16 *catQh = sa<bf16>(g_catQ_h), *catQl = sa<bf16>(g_catQ_l);
    bf16 *catG2h = sa<bf16>(g_catG2_h), *catG2l = sa<bf16>(g_catG2_l);
    bf16 *Vth = sa<bf16>(g_Vth), *Vtl = sa<bf16>(g_Vtl);
    unsigned char *cg = sa<unsigned char>(g_cg), *gc = sa<unsigned char>(g_gc);
    unsigned char *gq = sa<unsigned char>(g_gq), *qg = sa<unsigned char>(g_qg);
    float *PG = sa<float>(g_PG), *PC = sa<float>(g_PC), *PQ = sa<float>(g_PQ);
    float *G1 = sa<float>(g_G1);
    float *Ga = sa<float>(g_Ga), *Ca = sa<float>(g_Ca), *Qa = sa<float>(g_Qa);
    float *s1 = sa<float>(g_s1), *Ep1 = sa<float>(g_Ep1), *En1 = sa<float>(g_En1);
    float *s2 = sa<float>(g_s2), *Ep2 = sa<float>(g_Ep2), *En2 = sa<float>(g_En2);
    float *icS = sa<float>(g_icS);

    cudaFuncSetAttribute(gemm_mm<2,128,2>, cudaFuncAttributeMaxDynamicSharedMemorySize, 98304);
    cudaFuncSetAttribute(gemm_mm<3,128,0>, cudaFuncAttributeMaxDynamicSharedMemorySize, 131072);
    cudaFuncSetAttribute(gemm_fus, cudaFuncAttributeMaxDynamicSharedMemorySize, 131072);
    cudaFuncSetAttribute(attn_av2, cudaFuncAttributeMaxDynamicSharedMemorySize, 98304);

    const float* gloss    = (const float*)d_in[0];
    const float* clip     = (const float*)d_in[1];
    const float* question = (const float*)d_in[2];
    const int*   g2c      = (const int*)d_in[3];
    const int*   g2q      = (const int*)d_in[4];
    const float* aW[3]  = {(const float*)d_in[5], (const float*)d_in[8], (const float*)d_in[11]};
    const float* aA1[3] = {(const float*)d_in[6], (const float*)d_in[9], (const float*)d_in[12]};
    const float* aA2[3] = {(const float*)d_in[7], (const float*)d_in[10], (const float*)d_in[13]};
    const float* fusW  = (const float*)d_in[14];
    const float* fusU  = (const float*)d_in[15];
    const float* fusWf = (const float*)d_in[16];
    const float* fusUf = (const float*)d_in[17];

    prep_fusW<<<dim3(4096, 8), 256>>>(fusW, fusU, fusWf, fusUf);
    const size_t AWs = (size_t)NH * NF * HD;
    WTab wt;
    for (int l = 0; l < 2; l++)
        for (int a = 0; a < 3; a++) wt.W[l * 3 + a] = aW[a] + l * AWs;
    prep_attW6<<<dim3(1024, 6), 256>>>(wt);
    prep_adj_cg<<<dim3(4096, B_), 256>>>(g2c);
    prep_adj_gq<<<dim3(1024, B_), 256>>>(g2q);

    float* out = (float*)d_out;
    float* outG = out;
    float* outC = out + (size_t)B_ * NG * NF;
    float* outQ = outC + (size_t)B_ * NC * NF;

    for (int l = 0; l < 2; l++) {
        const float* Gin = l ? Ga : gloss;
        const float* Cin = l ? Ca : clip;
        const float* Qin = l ? Qa : question;
        float* Gout = l ? outG : Ga;
        float* Cout = l ? outC : Ca;
        float* Qout = l ? outQ : Qa;

        // 1. split inputs into cat col0 + transposed G
        SCTab sc;
        sc.src[0] = Gin; sc.dh[0] = catG1h; sc.dl[0] = catG1l; sc.tot[0] = 4096 * 512;
        sc.src[1] = Cin; sc.dh[1] = catCh;  sc.dl[1] = catCl;  sc.tot[1] = 4096 * 512;
        sc.src[2] = Qin; sc.dh[2] = catQh;  sc.dl[2] = catQl;  sc.tot[2] = 1024 * 512;
        split_cat3<<<dim3(8192, 3), 256>>>(sc);
        tsplit_k<<<dim3(2048, B_), 256>>>(Gin);

        // 2. adjT -> catC col512
        gemm_mm<2, 128, 2><<<dim3(4, 8, B_), 256, 98304>>>(
            adjTb, adjTb, Gth, Gtl, nullptr, catCh + 512, catCl + 512,
            1024, 1024, 1024, 1024, (long)NG * NC, (long)512 * 1024, (long)NC * 1024);

        // 3. projections: G x 3 slots (N=1536), C x slot0, Q x slots 1,2
        gemm_mm<3, 128, 0><<<dim3(12, 32, 1), 256, 131072>>>(
            catG1h, catG1l, aWh + (size_t)(l * 3) * 262144, aWl + (size_t)(l * 3) * 262144,
            PG, nullptr, nullptr, 512, 1024, 512, 1536, 0, 0, 0);
        gemm_mm<3, 128, 0><<<dim3(4, 32, 1), 256, 131072>>>(
            catCh, catCl, aWh + (size_t)(l * 3) * 262144, aWl + (size_t)(l * 3) * 262144,
            PC, nullptr, nullptr, 512, 1024, 512, 512, 0, 0, 0);
        gemm_mm<3, 128, 0><<<dim3(8, 8, 1), 256, 131072>>>(
            catQh, catQl, aWh + (size_t)(l * 3 + 1) * 262144, aWl + (size_t)(l * 3 + 1) * 262144,
            PQ, nullptr, nullptr, 512, 1024, 512, 1024, 0, 0, 0);

        // 4. scores (6 batched)
        SE6 se;
        se.e[0] = {PG, aA1[0] + l * 512, s1 + 0,     Ep1 + 0,     En1 + 0,     1024, 1536, 0};
        se.e[1] = {PC, aA2[0] + l * 512, s2 + 0,     Ep2 + 0,     En2 + 0,     1024, 512, 0};
        se.e[2] = {PQ, aA1[1] + l * 512, s1 + 32768, Ep1 + 32768, En1 + 32768, 256, 1024, 0};
        se.e[3] = {PG, aA2[1] + l * 512, s2 + 32768, Ep2 + 32768, En2 + 32768, 1024, 1536, 512};
        se.e[4] = {PG, aA1[2] + l * 512, s1 + 65536, Ep1 + 65536, En1 + 65536, 1024, 1536, 1024};
        se.e[5] = {PQ, aA2[2] + l * 512, s2 + 65536, Ep2 + 65536, En2 + 65536, 256, 1024, 512};
        scores6<<<dim3(128, 6), 256>>>(se);

        // 5. colsum (3 batched) -> icS
        CE3 ce;
        ce.e[0] = {cg, s1, Ep1, En1, s2, Ep2, En2, icS, 1024, 1024};
        ce.e[1] = {gq, s1 + 32768, Ep1 + 32768, En1 + 32768, s2 + 32768, Ep2 + 32768,
                   En2 + 32768, icS + 32768, 256, 1024};
        ce.e[2] = {qg, s1 + 65536, Ep1 + 65536, En1 + 65536, s2 + 65536, Ep2 + 65536,
                   En2 + 65536, icS + 65536, 1024, 256};
        colsum3<<<dim3(128, B_, 3), 256>>>(ce);

        // 6. V^T prep (3 batched)
        VE3 ve;
        ve.e[0] = {PC, icS,         Vth,           Vtl,           1024, 512, 0};
        ve.e[1] = {PG, icS + 32768, Vth + 2097152, Vtl + 2097152, 1024, 1536, 512};
        ve.e[2] = {PQ, icS + 65536, Vth + 4194304, Vtl + 4194304, 256, 1024, 512};
        vtprep3<<<dim3(256, 3, 32), 256>>>(ve);

        // 7. AV x3 (unbatched, known-good)
        attn_av2<<<dim3(1, 8, 32), 256, 98304>>>(
            gc, s1, Ep1, En1, s2, Ep2, En2, Vth, Vtl,
            catG1h + 512, catG1l + 512, 1024, 1024);
        attn_av2<<<dim3(1, 2, 32), 256, 98304>>>(
            qg, s1 + 32768, Ep1 + 32768, En1 + 32768, s2 + 32768, Ep2 + 32768, En2 + 32768,
            Vth + 2097152, Vtl + 2097152, catQh + 512, catQl + 512, 256, 1024);
        attn_av2<<<dim3(1, 8, 32), 256, 98304>>>(
            gq, s1 + 65536, Ep1 + 65536, En1 + 65536, s2 + 65536, Ep2 + 65536, En2 + 65536,
            Vth + 4194304, Vtl + 4194304, catG2h + 512, catG2l + 512, 1024, 256);

        // 8. fusions (gated epilogue)
        gemm_fus<<<dim3(8, 32), 256, 131072>>>(
            catCh, catCl, fWh + (size_t)(l*4+0)*1048576, fWl + (size_t)(l*4+0)*1048576,
            Cin, Cout, nullptr, nullptr, 0);
        gemm_fus<<<dim3(8, 32), 256, 131072>>>(
            catG1h, catG1l, fWh + (size_t)(l*4+1)*1048576, fWl + (size_t)(l*4+1)*1048576,
            Gin, G1, catG2h, catG2l, 1);
        gemm_fus<<<dim3(8, 8), 256, 131072>>>(
            catQh, catQl, fWh + (size_t)(l*4+2)*1048576, fWl + (size_t)(l*4+2)*1048576,
            Qin, Qout, nullptr, nullptr, 0);
        gemm_fus<<<dim3(8, 32), 256, 131072>>>(
            catG2h, catG2l, fWh + (size_t)(l*4+3)*1048576, fWl + (size_t)(l*4+3)*1048576,
            G1, Gout, nullptr, nullptr, 0);
    }
}